// round 2
// baseline (speedup 1.0000x reference)
#include <cuda_runtime.h>

// Problem constants
#define NG 4        // bands (G)
#define NB 128      // batch (B)
#define NNODE 30    // nodes (N)
#define NF 5000     // features (F)
#define NC 10       // out channels (C)
#define ROWS_G (NB*NNODE)   // 3840 rows per (mod,g)

// ---------------- device scratch (no allocations allowed) ----------------
__device__ float g_h[3 * NG * ROWS_G * NC];   // h for eeg/emg/cmc

typedef unsigned long long ull;

// ---------------- f32x2 packed helpers (sm_103a) ----------------
__device__ __forceinline__ ull pack2(float a, float b) {
    ull r;
    unsigned x = __float_as_uint(a), y = __float_as_uint(b);
    asm("mov.b64 %0, {%1, %2};" : "=l"(r) : "r"(x), "r"(y));
    return r;
}
__device__ __forceinline__ void unpack2(ull v, float& lo, float& hi) {
    unsigned x, y;
    asm("mov.b64 {%0, %1}, %2;" : "=r"(x), "=r"(y) : "l"(v));
    lo = __uint_as_float(x); hi = __uint_as_float(y);
}
__device__ __forceinline__ void ffma2(ull& d, ull a, ull b) {
    asm("fma.rn.f32x2 %0, %1, %2, %0;" : "+l"(d) : "l"(a), "l"(b));
}
__device__ __forceinline__ ull add2(ull a, ull b) {
    ull d;
    asm("add.rn.f32x2 %0, %1, %2;" : "=l"(d) : "l"(a), "l"(b));
    return d;
}

// =====================================================================
// Kernel 1: h[mod,g,row,c] = sum_k x[mod][g,row,k] * W[mod][g,k,c]
// 2880 blocks x 128 threads. Each warp owns 4 rows (block: 16 rows).
// W tile (KT k-values x 10 c) staged transposed in SMEM: Ws[c][k].
// Accumulators packed over (k,k+1) pairs via fma.rn.f32x2; x and w
// pairs come free out of float4 loads (no duplication movs).
// =====================================================================
#define KT 1024

__global__ __launch_bounds__(128, 3) void k1_gemm(
    const float* __restrict__ eeg, const float* __restrict__ emg,
    const float* __restrict__ cmc,
    const float* __restrict__ Weeg, const float* __restrict__ Wemg,
    const float* __restrict__ Wcmc)
{
    __shared__ float Ws[NC][KT];

    int blk = blockIdx.x;
    int mod = blk / 960;            // 240 row-blocks * 4 g
    int rem = blk % 960;
    int g   = rem / 240;
    int r0  = (rem % 240) * 16;

    const float* x = (mod == 0) ? eeg : ((mod == 1) ? emg : cmc);
    const float* W = ((mod == 0) ? Weeg : ((mod == 1) ? Wemg : Wcmc)) + (size_t)g * NF * NC;

    int tid  = threadIdx.x;
    int lane = tid & 31;
    int wid  = tid >> 5;

    size_t rowg = (size_t)g * ROWS_G + r0 + wid * 4;
    const float* p0 = x + rowg * NF;
    const float* p1 = p0 + NF;
    const float* p2 = p1 + NF;
    const float* p3 = p2 + NF;

    ull acc[4][NC];
#pragma unroll
    for (int r = 0; r < 4; r++)
#pragma unroll
        for (int c = 0; c < NC; c++) acc[r][c] = 0ull;

#pragma unroll 1
    for (int tile = 0; tile < 5; ++tile) {
        int kbase = tile * KT;
        int klen  = (NF - kbase < KT) ? (NF - kbase) : KT;   // 1024 or 904
        int nel   = klen * NC;
        const float* Wt = W + (size_t)kbase * NC;
        for (int idx = tid; idx < nel; idx += 128) {
            Ws[idx % NC][idx / NC] = Wt[idx];
        }
        __syncthreads();

        const float* q0 = p0 + kbase;
        const float* q1 = p1 + kbase;
        const float* q2 = p2 + kbase;
        const float* q3 = p3 + kbase;

        if (klen == KT) {
            // 8 steps of 128 k, software-pipelined one step ahead
            int kl = lane * 4;
            float4 xa0 = *(const float4*)(q0 + kl);
            float4 xa1 = *(const float4*)(q1 + kl);
            float4 xa2 = *(const float4*)(q2 + kl);
            float4 xa3 = *(const float4*)(q3 + kl);
#pragma unroll 2
            for (int s = 0; s < 8; ++s) {
                float4 xb0, xb1, xb2, xb3;
                if (s < 7) {
                    int kn = (s + 1) * 128 + lane * 4;
                    xb0 = *(const float4*)(q0 + kn);
                    xb1 = *(const float4*)(q1 + kn);
                    xb2 = *(const float4*)(q2 + kn);
                    xb3 = *(const float4*)(q3 + kn);
                }
                int ks = s * 128 + lane * 4;
                ull x01_0 = pack2(xa0.x, xa0.y), x23_0 = pack2(xa0.z, xa0.w);
                ull x01_1 = pack2(xa1.x, xa1.y), x23_1 = pack2(xa1.z, xa1.w);
                ull x01_2 = pack2(xa2.x, xa2.y), x23_2 = pack2(xa2.z, xa2.w);
                ull x01_3 = pack2(xa3.x, xa3.y), x23_3 = pack2(xa3.z, xa3.w);
#pragma unroll
                for (int c = 0; c < NC; c++) {
                    float4 w = *(const float4*)&Ws[c][ks];
                    ull w01 = pack2(w.x, w.y), w23 = pack2(w.z, w.w);
                    ffma2(acc[0][c], x01_0, w01); ffma2(acc[0][c], x23_0, w23);
                    ffma2(acc[1][c], x01_1, w01); ffma2(acc[1][c], x23_1, w23);
                    ffma2(acc[2][c], x01_2, w01); ffma2(acc[2][c], x23_2, w23);
                    ffma2(acc[3][c], x01_3, w01); ffma2(acc[3][c], x23_3, w23);
                }
                if (s < 7) { xa0 = xb0; xa1 = xb1; xa2 = xb2; xa3 = xb3; }
            }
        } else {
            // tail tile: klen = 904 (multiple of 4), predicated float4 steps
#pragma unroll 1
            for (int s = 0; s < 8; ++s) {
                int kl = s * 128 + lane * 4;
                if (kl < klen) {
                    float4 x0 = *(const float4*)(q0 + kl);
                    float4 x1 = *(const float4*)(q1 + kl);
                    float4 x2 = *(const float4*)(q2 + kl);
                    float4 x3 = *(const float4*)(q3 + kl);
                    ull x01_0 = pack2(x0.x, x0.y), x23_0 = pack2(x0.z, x0.w);
                    ull x01_1 = pack2(x1.x, x1.y), x23_1 = pack2(x1.z, x1.w);
                    ull x01_2 = pack2(x2.x, x2.y), x23_2 = pack2(x2.z, x2.w);
                    ull x01_3 = pack2(x3.x, x3.y), x23_3 = pack2(x3.z, x3.w);
#pragma unroll
                    for (int c = 0; c < NC; c++) {
                        float4 w = *(const float4*)&Ws[c][kl];
                        ull w01 = pack2(w.x, w.y), w23 = pack2(w.z, w.w);
                        ffma2(acc[0][c], x01_0, w01); ffma2(acc[0][c], x23_0, w23);
                        ffma2(acc[1][c], x01_1, w01); ffma2(acc[1][c], x23_1, w23);
                        ffma2(acc[2][c], x01_2, w01); ffma2(acc[2][c], x23_2, w23);
                        ffma2(acc[3][c], x01_3, w01); ffma2(acc[3][c], x23_3, w23);
                    }
                }
            }
        }
        __syncthreads();
    }

    // cross-lane reduction (packed), then lo+hi fold, store
    size_t outbase = ((size_t)(mod * NG + g) * ROWS_G + r0 + wid * 4) * NC;
#pragma unroll
    for (int r = 0; r < 4; r++) {
#pragma unroll
        for (int c = 0; c < NC; c++) {
            ull v = acc[r][c];
#pragma unroll
            for (int off = 16; off > 0; off >>= 1)
                v = add2(v, __shfl_down_sync(0xffffffffu, v, off));
            if (lane == 0) {
                float lo, hi;
                unpack2(v, lo, hi);
                g_h[outbase + (size_t)r * NC + c] = lo + hi;
            }
        }
    }
}

// =====================================================================
// Kernel 2+3 fused: per b (128 blocks, 256 threads = 4 groups of 64).
// Group g: GAT(eeg), GAT(emg), CMC GCN, modality MoE gate -> band feats.
// Then all 256 threads: band MoE gate, pooling, MLP head.
// =====================================================================
#define GBAR() asm volatile("bar.sync %0, 64;" :: "r"(gid + 1) : "memory")

__global__ __launch_bounds__(256) void k23_rest(
    const float* __restrict__ wpli_eeg, const float* __restrict__ wpli_emg,
    const float* __restrict__ cmc_train,
    const float* __restrict__ a_eeg, const float* __restrict__ a_emg,
    const float* __restrict__ b_cmc,
    const float* __restrict__ g0w1, const float* __restrict__ g0b1,
    const float* __restrict__ g0w2, const float* __restrict__ g0b2,
    const float* __restrict__ g1w1, const float* __restrict__ g1b1,
    const float* __restrict__ g1w2, const float* __restrict__ g1b2,
    const float* __restrict__ mlp0w, const float* __restrict__ mlp0b,
    const float* __restrict__ mlp1w, const float* __restrict__ mlp1b,
    const float* __restrict__ mlp2w, const float* __restrict__ mlp2b,
    const float* __restrict__ bng, const float* __restrict__ bnb,
    float* __restrict__ out)
{
    int b   = blockIdx.x;
    int tid = threadIdx.x;
    int gid = tid >> 6;           // band group 0..3
    int lt  = tid & 63;

    __shared__ float hbuf[NG][NNODE][NC];          // current modality h
    __shared__ float fE[NG][NNODE][NC];
    __shared__ float fM[NG][NNODE][NC];
    __shared__ float fC[NG][NNODE][NC];
    __shared__ float buf[NG][NNODE][NNODE];        // cor, then att, then hg1
    __shared__ float f1s[NG][NNODE], f2s[NG][NNODE];
    __shared__ float band[NNODE][40];
    __shared__ float gs[NNODE][4];
    __shared__ float feat[40];
    __shared__ float h1[256];
    __shared__ float h2[32];

    int g = gid;

    // --- cor = mean_t cmc_train[t,g,:,:] ---
    for (int i = lt; i < NNODE * NNODE; i += 64) {
        float s = 0.f;
#pragma unroll
        for (int t = 0; t < 8; t++)
            s += cmc_train[(size_t)t * (NG * NNODE * NNODE) + (size_t)g * (NNODE * NNODE) + i];
        buf[g][i / NNODE][i % NNODE] = s * 0.125f;
    }
    // --- load hC ---
    {
        size_t hb = ((size_t)(2 * NG + g) * ROWS_G + (size_t)b * NNODE) * NC;
        for (int i = lt; i < NNODE * NC; i += 64)
            hbuf[g][i / NC][i % NC] = g_h[hb + i];
    }
    GBAR();
    // --- fC = cor @ hC + b_cmc ---
    for (int idx = lt; idx < NNODE * NC; idx += 64) {
        int i = idx / NC, c = idx % NC;
        float s = 0.f;
        for (int j = 0; j < NNODE; j++) s += buf[g][i][j] * hbuf[g][j][c];
        fC[g][i][c] = s + b_cmc[g * NC + c];
    }
    GBAR();

    // --- GAT experts (eeg then emg), att reuses buf ---
    for (int m = 0; m < 2; ++m) {
        const float* a   = ((m == 0) ? a_eeg : a_emg) + g * 2 * NC;
        const float* adj = ((m == 0) ? wpli_eeg : wpli_emg) + g * NNODE * NNODE;
        size_t hb = ((size_t)(m * NG + g) * ROWS_G + (size_t)b * NNODE) * NC;
        for (int i = lt; i < NNODE * NC; i += 64)
            hbuf[g][i / NC][i % NC] = g_h[hb + i];
        GBAR();
        if (lt < NNODE) {
            float s1 = 0.f, s2 = 0.f;
#pragma unroll
            for (int c = 0; c < NC; c++) {
                s1 += hbuf[g][lt][c] * a[c];
                s2 += hbuf[g][lt][c] * a[NC + c];
            }
            f1s[g][lt] = s1; f2s[g][lt] = s2;
        }
        GBAR();
        if (lt < NNODE) {                 // softmax over i, column j = lt
            int j = lt;
            float mx = -1e30f;
            for (int i = 0; i < NNODE; i++) {
                float v;
                if (adj[i * NNODE + j] > 0.f) {
                    float e = f1s[g][i] + f2s[g][j];
                    v = (e > 0.f) ? e : 0.1f * e;
                } else {
                    v = -1e12f;
                }
                buf[g][i][j] = v;
                mx = fmaxf(mx, v);
            }
            float s = 0.f;
            for (int i = 0; i < NNODE; i++) {
                float ex = expf(buf[g][i][j] - mx);
                buf[g][i][j] = ex; s += ex;
            }
            float inv = 1.f / s;
            for (int i = 0; i < NNODE; i++) buf[g][i][j] *= inv;
        }
        GBAR();
        for (int idx = lt; idx < NNODE * NC; idx += 64) {
            int i = idx / NC, c = idx % NC;
            float s = 0.f;
            for (int j = 0; j < NNODE; j++) s += buf[g][i][j] * hbuf[g][j][c];
            if (m == 0) fE[g][i][c] = fmaxf(s, 0.f);
            else        fM[g][i][c] = fmaxf(s, 0.f);
        }
        GBAR();
    }

    // --- gating0: two threads per node (each 32 hidden units) ---
    {
        int n    = (lt >> 1 < NNODE) ? (lt >> 1) : 0;   // clamp so all lanes converge
        int half = lt & 1;
        float fcat[30];
#pragma unroll
        for (int k = 0; k < 10; k++) {
            fcat[k]      = fE[g][n][k];
            fcat[10 + k] = fM[g][n][k];
            fcat[20 + k] = fC[g][n][k];
        }
        float l0 = 0.f, l1 = 0.f, l2 = 0.f;
#pragma unroll 4
        for (int oi = 0; oi < 32; oi++) {
            int o = half * 32 + oi;
            float s = g0b1[o];
#pragma unroll
            for (int k = 0; k < 30; k++) s += fcat[k] * g0w1[k * 64 + o];
            s = fmaxf(s, 0.f);
            l0 += s * g0w2[o * 3 + 0];
            l1 += s * g0w2[o * 3 + 1];
            l2 += s * g0w2[o * 3 + 2];
        }
        l0 += __shfl_down_sync(0xffffffffu, l0, 1);
        l1 += __shfl_down_sync(0xffffffffu, l1, 1);
        l2 += __shfl_down_sync(0xffffffffu, l2, 1);
        if (half == 0 && (lt >> 1) < NNODE) {
            l0 += g0b2[0]; l1 += g0b2[1]; l2 += g0b2[2];
            float mx = fmaxf(l0, fmaxf(l1, l2));
            float e0 = expf(l0 - mx), e1 = expf(l1 - mx), e2 = expf(l2 - mx);
            float inv = 1.f / (e0 + e1 + e2);
            e0 *= inv; e1 *= inv; e2 *= inv;
#pragma unroll
            for (int c = 0; c < NC; c++)
                band[n][g * NC + c] = e0 * fE[g][n][c] + e1 * fM[g][n][c] + e2 * fC[g][n][c];
        }
    }
    __syncthreads();

    // --- head: band gating + pool + MLP (all 256 threads) ---
    float* hg1 = &buf[0][0][0];   // 3600 floats scratch >= 1920 needed
    for (int idx = tid; idx < NNODE * 64; idx += 256) {
        int n = idx / 64, o = idx % 64;
        float s = g1b1[o];
#pragma unroll
        for (int k = 0; k < 40; k++) s += band[n][k] * g1w1[k * 64 + o];
        hg1[n * 64 + o] = fmaxf(s, 0.f);
    }
    __syncthreads();
    if (tid < NNODE) {
        float l[4];
#pragma unroll
        for (int e = 0; e < 4; e++) l[e] = g1b2[e];
        for (int o = 0; o < 64; o++) {
            float v = hg1[tid * 64 + o];
#pragma unroll
            for (int e = 0; e < 4; e++) l[e] += v * g1w2[o * 4 + e];
        }
        float mx = fmaxf(fmaxf(l[0], l[1]), fmaxf(l[2], l[3]));
        float s = 0.f;
#pragma unroll
        for (int e = 0; e < 4; e++) { l[e] = expf(l[e] - mx); s += l[e]; }
        float inv = 1.f / s;
#pragma unroll
        for (int e = 0; e < 4; e++) gs[tid][e] = l[e] * inv;
    }
    __syncthreads();
    if (tid < 40) {
        float s = 0.f;
        for (int n = 0; n < NNODE; n++) s += band[n][tid] * gs[n][tid / 10];
        feat[tid] = s * (1.f / 30.f);
    }
    __syncthreads();
    if (tid < 256) {
        int o = tid;
        float s = mlp0b[o];
#pragma unroll
        for (int k = 0; k < 40; k++) s += feat[k] * mlp0w[k * 256 + o];
        h1[o] = fmaxf(s, 0.f);
    }
    __syncthreads();
    if (tid < 32) {
        float s = mlp1b[tid];
        for (int k = 0; k < 256; k++) s += h1[k] * mlp1w[k * 32 + tid];
        s = fmaxf(s, 0.f);
        h2[tid] = s * (bng[tid] * rsqrtf(1.f + 1e-5f)) + bnb[tid];
    }
    __syncthreads();
    if (tid < 4) {
        float s = mlp2b[tid];
#pragma unroll
        for (int k = 0; k < 32; k++) s += h2[k] * mlp2w[k * 4 + tid];
        out[b * 4 + tid] = s;
    }
}

// =====================================================================
extern "C" void kernel_launch(void* const* d_in, const int* in_sizes, int n_in,
                              void* d_out, int out_size)
{
    const float* eeg       = (const float*)d_in[0];
    const float* wpli_eeg  = (const float*)d_in[1];
    const float* emg       = (const float*)d_in[2];
    const float* wpli_emg  = (const float*)d_in[3];
    const float* cmc       = (const float*)d_in[4];
    const float* cmc_train = (const float*)d_in[5];
    const float* W_eeg     = (const float*)d_in[6];
    const float* a_eeg     = (const float*)d_in[7];
    const float* W_emg     = (const float*)d_in[8];
    const float* a_emg     = (const float*)d_in[9];
    const float* W_cmc     = (const float*)d_in[10];
    const float* b_cmc     = (const float*)d_in[11];
    const float* g0w1      = (const float*)d_in[12];
    const float* g0b1      = (const float*)d_in[13];
    const float* g0w2      = (const float*)d_in[14];
    const float* g0b2      = (const float*)d_in[15];
    const float* g1w1      = (const float*)d_in[16];
    const float* g1b1      = (const float*)d_in[17];
    const float* g1w2      = (const float*)d_in[18];
    const float* g1b2      = (const float*)d_in[19];
    const float* mlp0w     = (const float*)d_in[20];
    const float* mlp0b     = (const float*)d_in[21];
    const float* mlp1w     = (const float*)d_in[22];
    const float* mlp1b     = (const float*)d_in[23];
    const float* mlp2w     = (const float*)d_in[24];
    const float* mlp2b     = (const float*)d_in[25];
    const float* bng       = (const float*)d_in[26];
    const float* bnb       = (const float*)d_in[27];

    k1_gemm<<<2880, 128>>>(eeg, emg, cmc, W_eeg, W_emg, W_cmc);

    k23_rest<<<NB, 256>>>(wpli_eeg, wpli_emg, cmc_train,
                          a_eeg, a_emg, b_cmc,
                          g0w1, g0b1, g0w2, g0b2,
                          g1w1, g1b1, g1w2, g1b2,
                          mlp0w, mlp0b, mlp1w, mlp1b, mlp2w, mlp2b,
                          bng, bnb, (float*)d_out);
}

// round 3
// speedup vs baseline: 2.3731x; 2.3731x over previous
#include <cuda_runtime.h>

// Problem constants
#define NG 4        // bands (G)
#define NB 128      // batch (B)
#define NNODE 30    // nodes (N)
#define NF 5000     // features (F)
#define NC 10       // out channels (C)
#define ROWS_G (NB*NNODE)   // 3840 rows per (mod,g)

// ---------------- device scratch (no allocations allowed) ----------------
__device__ float g_h[3 * NG * ROWS_G * NC];      // h for eeg/emg/cmc
__device__ float g_fused[NG * NB * NNODE * NC];  // fused modality features
__device__ float g_Wt[12 * NC * NF];             // W transposed: [(mod*4+g)*10+c][k]
__device__ float g_cor[NG * NNODE * NNODE];      // mean over T of cmc_train

typedef unsigned long long ull;

// ---------------- f32x2 packed helpers (sm_103a) ----------------
__device__ __forceinline__ ull pack2(float a, float b) {
    ull r;
    unsigned x = __float_as_uint(a), y = __float_as_uint(b);
    asm("mov.b64 %0, {%1, %2};" : "=l"(r) : "r"(x), "r"(y));
    return r;
}
__device__ __forceinline__ ull dup2(float a) {
    ull r;
    unsigned x = __float_as_uint(a);
    asm("mov.b64 %0, {%1, %1};" : "=l"(r) : "r"(x));
    return r;
}
__device__ __forceinline__ void unpack2(ull v, float& lo, float& hi) {
    unsigned x, y;
    asm("mov.b64 {%0, %1}, %2;" : "=r"(x), "=r"(y) : "l"(v));
    lo = __uint_as_float(x); hi = __uint_as_float(y);
}
__device__ __forceinline__ void ffma2(ull& d, ull a, ull b) {
    asm("fma.rn.f32x2 %0, %1, %2, %0;" : "+l"(d) : "l"(a), "l"(b));
}
__device__ __forceinline__ ull add2(ull a, ull b) {
    ull d;
    asm("add.rn.f32x2 %0, %1, %2;" : "=l"(d) : "l"(a), "l"(b));
    return d;
}

// =====================================================================
// Kernel 0: prep. Transpose W -> g_Wt [mg][c][k]; cor = mean_t cmc_train.
// =====================================================================
__global__ __launch_bounds__(256) void k0_prep(
    const float* __restrict__ Weeg, const float* __restrict__ Wemg,
    const float* __restrict__ Wcmc, const float* __restrict__ cmc_train)
{
    int idx = blockIdx.x * 256 + threadIdx.x;
    if (idx < 12 * NC * NF) {
        int mg  = idx / (NC * NF);
        int rem = idx % (NC * NF);
        int c = rem / NF, k = rem % NF;
        int mod = mg >> 2, g = mg & 3;
        const float* W = (mod == 0) ? Weeg : ((mod == 1) ? Wemg : Wcmc);
        g_Wt[idx] = W[((size_t)g * NF + k) * NC + c];
    } else if (idx < 12 * NC * NF + NG * NNODE * NNODE) {
        int i = idx - 12 * NC * NF;
        float s = 0.f;
#pragma unroll
        for (int t = 0; t < 8; t++)
            s += cmc_train[(size_t)t * (NG * NNODE * NNODE) + i];
        g_cor[i] = s * 0.125f;
    }
}

// =====================================================================
// Kernel 1: h[mod,g,row,c] = sum_k x[row,k] * W[k,c]
// 2880 blocks x 128 threads, no smem, no syncs.
// Warp owns 4 rows. Accumulators packed over row-pairs (rows 0,1 | 2,3):
// acc[2][10] ull = 40 regs. x streamed via __ldcs (evict-first, keeps Wt
// in L1); w via __ldg from pre-transposed g_Wt (L1-resident, 200KB/(mod,g)).
// Depth-2 rolling prefetch of x.
// =====================================================================
__global__ __launch_bounds__(128, 4) void k1_gemm(
    const float* __restrict__ eeg, const float* __restrict__ emg,
    const float* __restrict__ cmc)
{
    int blk = blockIdx.x;
    int mod = blk / 960;           // 4 g * 240 row-blocks
    int rem = blk % 960;
    int g   = rem / 240;
    int r0  = (rem % 240) * 16;

    const float* x = (mod == 0) ? eeg : ((mod == 1) ? emg : cmc);

    int tid  = threadIdx.x;
    int lane = tid & 31;
    int wid  = tid >> 5;
    int kl   = lane * 4;

    int r0w = r0 + wid * 4;
    const float* q0 = x + ((size_t)g * ROWS_G + r0w) * NF;
    const float* q1 = q0 + NF;
    const float* q2 = q1 + NF;
    const float* q3 = q2 + NF;
    const float* wp = g_Wt + (size_t)(mod * NG + g) * (NC * NF) + kl;

    ull a01[NC], a23[NC];
#pragma unroll
    for (int c = 0; c < NC; c++) { a01[c] = 0ull; a23[c] = 0ull; }

    // depth-2 rolling prefetch
    float4 xa0 = __ldcs((const float4*)(q0 + kl));
    float4 xa1 = __ldcs((const float4*)(q1 + kl));
    float4 xa2 = __ldcs((const float4*)(q2 + kl));
    float4 xa3 = __ldcs((const float4*)(q3 + kl));
    float4 xb0 = __ldcs((const float4*)(q0 + 128 + kl));
    float4 xb1 = __ldcs((const float4*)(q1 + 128 + kl));
    float4 xb2 = __ldcs((const float4*)(q2 + 128 + kl));
    float4 xb3 = __ldcs((const float4*)(q3 + 128 + kl));

#pragma unroll 3
    for (int s = 0; s < 39; ++s) {      // 39*128 = 4992 k
        float4 xc0, xc1, xc2, xc3;
        if (s < 37) {
            int kn = (s + 2) * 128 + kl;
            xc0 = __ldcs((const float4*)(q0 + kn));
            xc1 = __ldcs((const float4*)(q1 + kn));
            xc2 = __ldcs((const float4*)(q2 + kn));
            xc3 = __ldcs((const float4*)(q3 + kn));
        }
        // pack x across row-pairs (rows 0,1) and (2,3)
        ull x01x = pack2(xa0.x, xa1.x), x01y = pack2(xa0.y, xa1.y);
        ull x01z = pack2(xa0.z, xa1.z), x01w = pack2(xa0.w, xa1.w);
        ull x23x = pack2(xa2.x, xa3.x), x23y = pack2(xa2.y, xa3.y);
        ull x23z = pack2(xa2.z, xa3.z), x23w = pack2(xa2.w, xa3.w);
        int ks = s * 128;
#pragma unroll
        for (int c = 0; c < NC; c++) {
            float4 w = __ldg((const float4*)(wp + (size_t)c * NF + ks));
            ull wx = dup2(w.x), wy = dup2(w.y), wz = dup2(w.z), ww = dup2(w.w);
            ffma2(a01[c], x01x, wx); ffma2(a01[c], x01y, wy);
            ffma2(a01[c], x01z, wz); ffma2(a01[c], x01w, ww);
            ffma2(a23[c], x23x, wx); ffma2(a23[c], x23y, wy);
            ffma2(a23[c], x23z, wz); ffma2(a23[c], x23w, ww);
        }
        xa0 = xb0; xa1 = xb1; xa2 = xb2; xa3 = xb3;
        xb0 = xc0; xb1 = xc1; xb2 = xc2; xb3 = xc3;
    }

    // tail: k = 4992..4999 (2 float4s), lanes 0..1
    if (lane < 2) {
        int ks = 4992 + kl;
        float4 x0 = __ldcs((const float4*)(q0 + ks));
        float4 x1 = __ldcs((const float4*)(q1 + ks));
        float4 x2 = __ldcs((const float4*)(q2 + ks));
        float4 x3 = __ldcs((const float4*)(q3 + ks));
        ull x01x = pack2(x0.x, x1.x), x01y = pack2(x0.y, x1.y);
        ull x01z = pack2(x0.z, x1.z), x01w = pack2(x0.w, x1.w);
        ull x23x = pack2(x2.x, x3.x), x23y = pack2(x2.y, x3.y);
        ull x23z = pack2(x2.z, x3.z), x23w = pack2(x2.w, x3.w);
#pragma unroll
        for (int c = 0; c < NC; c++) {
            float4 w = __ldg((const float4*)(wp + (size_t)c * NF + 4992));
            ull wx = dup2(w.x), wy = dup2(w.y), wz = dup2(w.z), ww = dup2(w.w);
            ffma2(a01[c], x01x, wx); ffma2(a01[c], x01y, wy);
            ffma2(a01[c], x01z, wz); ffma2(a01[c], x01w, ww);
            ffma2(a23[c], x23x, wx); ffma2(a23[c], x23y, wy);
            ffma2(a23[c], x23z, wz); ffma2(a23[c], x23w, ww);
        }
    }

    // cross-lane reduction; lo/hi are DIFFERENT rows (no fold)
    size_t outbase = ((size_t)(mod * NG + g) * ROWS_G + r0w) * NC;
#pragma unroll
    for (int c = 0; c < NC; c++) {
        ull v = a01[c];
#pragma unroll
        for (int off = 16; off > 0; off >>= 1)
            v = add2(v, __shfl_down_sync(0xffffffffu, v, off));
        if (lane == 0) {
            float lo, hi; unpack2(v, lo, hi);
            g_h[outbase + c]      = lo;
            g_h[outbase + NC + c] = hi;
        }
        v = a23[c];
#pragma unroll
        for (int off = 16; off > 0; off >>= 1)
            v = add2(v, __shfl_down_sync(0xffffffffu, v, off));
        if (lane == 0) {
            float lo, hi; unpack2(v, lo, hi);
            g_h[outbase + 2 * NC + c] = lo;
            g_h[outbase + 3 * NC + c] = hi;
        }
    }
}

// =====================================================================
// Kernel 2: per (g,b): GAT(eeg), GAT(emg), CMC GCN, modality MoE gate.
// Grid: (128, 4), 128 threads.
// =====================================================================
__global__ __launch_bounds__(128) void k2_gat(
    const float* __restrict__ wpli_eeg, const float* __restrict__ wpli_emg,
    const float* __restrict__ a_eeg, const float* __restrict__ a_emg,
    const float* __restrict__ b_cmc,
    const float* __restrict__ g0w1, const float* __restrict__ g0b1,
    const float* __restrict__ g0w2, const float* __restrict__ g0b2)
{
    int b = blockIdx.x, g = blockIdx.y;
    int tid = threadIdx.x;

    __shared__ float hE[NNODE][NC], hM[NNODE][NC], hC[NNODE][NC];
    __shared__ float fE[NNODE][NC], fM[NNODE][NC], fC[NNODE][NC];
    __shared__ float att[NNODE][NNODE];
    __shared__ float cor[NNODE][NNODE];
    __shared__ float f1[NNODE], f2[NNODE];
    __shared__ float hg[NNODE][64];

    size_t hbE = ((size_t)(0 * NG + g) * ROWS_G + (size_t)b * NNODE) * NC;
    size_t hbM = ((size_t)(1 * NG + g) * ROWS_G + (size_t)b * NNODE) * NC;
    size_t hbC = ((size_t)(2 * NG + g) * ROWS_G + (size_t)b * NNODE) * NC;
    for (int i = tid; i < NNODE * NC; i += 128) {
        hE[i / NC][i % NC] = g_h[hbE + i];
        hM[i / NC][i % NC] = g_h[hbM + i];
        hC[i / NC][i % NC] = g_h[hbC + i];
    }
    for (int i = tid; i < NNODE * NNODE; i += 128)
        cor[i / NNODE][i % NNODE] = g_cor[g * NNODE * NNODE + i];
    __syncthreads();

    // CMC expert: cor @ hC + b (no activation)
    for (int idx = tid; idx < NNODE * NC; idx += 128) {
        int i = idx / NC, c = idx % NC;
        float s = 0.f;
        for (int j = 0; j < NNODE; j++) s += cor[i][j] * hC[j][c];
        fC[i][c] = s + b_cmc[g * NC + c];
    }

    // GAT experts (eeg, emg)
    for (int m = 0; m < 2; ++m) {
        const float* a   = ((m == 0) ? a_eeg : a_emg) + g * 2 * NC;
        const float* adj = ((m == 0) ? wpli_eeg : wpli_emg) + g * NNODE * NNODE;
        float (*h)[NC] = (m == 0) ? hE : hM;
        float (*f)[NC] = (m == 0) ? fE : fM;
        __syncthreads();
        if (tid < NNODE) {
            float s1 = 0.f, s2 = 0.f;
#pragma unroll
            for (int c = 0; c < NC; c++) {
                s1 += h[tid][c] * a[c];
                s2 += h[tid][c] * a[NC + c];
            }
            f1[tid] = s1; f2[tid] = s2;
        }
        __syncthreads();
        if (tid < NNODE) {           // softmax over i, column j = tid
            int j = tid;
            float mx = -1e30f;
            for (int i = 0; i < NNODE; i++) {
                float v;
                if (adj[i * NNODE + j] > 0.f) {
                    float e = f1[i] + f2[j];
                    v = (e > 0.f) ? e : 0.1f * e;   // LeakyReLU(0.1)
                } else {
                    v = -1e12f;
                }
                att[i][j] = v;
                mx = fmaxf(mx, v);
            }
            float s = 0.f;
            for (int i = 0; i < NNODE; i++) {
                float ex = expf(att[i][j] - mx);
                att[i][j] = ex; s += ex;
            }
            float inv = 1.f / s;
            for (int i = 0; i < NNODE; i++) att[i][j] *= inv;
        }
        __syncthreads();
        for (int idx = tid; idx < NNODE * NC; idx += 128) {
            int i = idx / NC, c = idx % NC;
            float s = 0.f;
            for (int j = 0; j < NNODE; j++) s += att[i][j] * h[j][c];
            f[i][c] = fmaxf(s, 0.f);
        }
    }
    __syncthreads();

    // gating0
    for (int idx = tid; idx < NNODE * 64; idx += 128) {
        int n = idx / 64, o = idx % 64;
        float s = g0b1[o];
#pragma unroll
        for (int k = 0; k < 10; k++) s += fE[n][k] * g0w1[k * 64 + o];
#pragma unroll
        for (int k = 0; k < 10; k++) s += fM[n][k] * g0w1[(10 + k) * 64 + o];
#pragma unroll
        for (int k = 0; k < 10; k++) s += fC[n][k] * g0w1[(20 + k) * 64 + o];
        hg[n][o] = fmaxf(s, 0.f);
    }
    __syncthreads();
    if (tid < NNODE) {
        int n = tid;
        float l0 = g0b2[0], l1 = g0b2[1], l2 = g0b2[2];
        for (int o = 0; o < 64; o++) {
            float v = hg[n][o];
            l0 += v * g0w2[o * 3 + 0];
            l1 += v * g0w2[o * 3 + 1];
            l2 += v * g0w2[o * 3 + 2];
        }
        float mx = fmaxf(l0, fmaxf(l1, l2));
        float e0 = expf(l0 - mx), e1 = expf(l1 - mx), e2 = expf(l2 - mx);
        float inv = 1.f / (e0 + e1 + e2);
        e0 *= inv; e1 *= inv; e2 *= inv;
        size_t ob = ((size_t)(g * NB + b) * NNODE + n) * NC;
#pragma unroll
        for (int c = 0; c < NC; c++)
            g_fused[ob + c] = e0 * fE[n][c] + e1 * fM[n][c] + e2 * fC[n][c];
    }
}

// =====================================================================
// Kernel 3: per b: band MoE gate, node pooling, MLP head + BN
// Grid: 128 blocks, 256 threads.
// =====================================================================
__global__ __launch_bounds__(256) void k3_head(
    const float* __restrict__ g1w1, const float* __restrict__ g1b1,
    const float* __restrict__ g1w2, const float* __restrict__ g1b2,
    const float* __restrict__ mlp0w, const float* __restrict__ mlp0b,
    const float* __restrict__ mlp1w, const float* __restrict__ mlp1b,
    const float* __restrict__ mlp2w, const float* __restrict__ mlp2b,
    const float* __restrict__ bng, const float* __restrict__ bnb,
    float* __restrict__ out)
{
    int b = blockIdx.x, tid = threadIdx.x;
    __shared__ float band[NNODE][40];
    __shared__ float hg[NNODE][64];
    __shared__ float gs[NNODE][4];
    __shared__ float feat[40];
    __shared__ float h1[256];
    __shared__ float h2[32];

    for (int idx = tid; idx < NNODE * 40; idx += 256) {
        int n = idx / 40, d = idx % 40, g = d / 10, c = d % 10;
        band[n][d] = g_fused[((size_t)(g * NB + b) * NNODE + n) * NC + c];
    }
    __syncthreads();

    for (int idx = tid; idx < NNODE * 64; idx += 256) {
        int n = idx / 64, o = idx % 64;
        float s = g1b1[o];
#pragma unroll
        for (int k = 0; k < 40; k++) s += band[n][k] * g1w1[k * 64 + o];
        hg[n][o] = fmaxf(s, 0.f);
    }
    __syncthreads();
    if (tid < NNODE) {
        float l[4];
#pragma unroll
        for (int e = 0; e < 4; e++) l[e] = g1b2[e];
        for (int o = 0; o < 64; o++) {
            float v = hg[tid][o];
#pragma unroll
            for (int e = 0; e < 4; e++) l[e] += v * g1w2[o * 4 + e];
        }
        float mx = fmaxf(fmaxf(l[0], l[1]), fmaxf(l[2], l[3]));
        float s = 0.f;
#pragma unroll
        for (int e = 0; e < 4; e++) { l[e] = expf(l[e] - mx); s += l[e]; }
        float inv = 1.f / s;
#pragma unroll
        for (int e = 0; e < 4; e++) gs[tid][e] = l[e] * inv;
    }
    __syncthreads();
    if (tid < 40) {
        float s = 0.f;
        for (int n = 0; n < NNODE; n++) s += band[n][tid] * gs[n][tid / 10];
        feat[tid] = s * (1.f / 30.f);
    }
    __syncthreads();
    {
        int o = tid;
        float s = mlp0b[o];
#pragma unroll
        for (int k = 0; k < 40; k++) s += feat[k] * mlp0w[k * 256 + o];
        h1[o] = fmaxf(s, 0.f);
    }
    __syncthreads();
    if (tid < 32) {
        float s = mlp1b[tid];
        for (int k = 0; k < 256; k++) s += h1[k] * mlp1w[k * 32 + tid];
        s = fmaxf(s, 0.f);
        h2[tid] = s * (bng[tid] * rsqrtf(1.f + 1e-5f)) + bnb[tid];
    }
    __syncthreads();
    if (tid < 4) {
        float s = mlp2b[tid];
#pragma unroll
        for (int k = 0; k < 32; k++) s += h2[k] * mlp2w[k * 4 + tid];
        out[b * 4 + tid] = s;
    }
}

// =====================================================================
extern "C" void kernel_launch(void* const* d_in, const int* in_sizes, int n_in,
                              void* d_out, int out_size)
{
    const float* eeg       = (const float*)d_in[0];
    const float* wpli_eeg  = (const float*)d_in[1];
    const float* emg       = (const float*)d_in[2];
    const float* wpli_emg  = (const float*)d_in[3];
    const float* cmc       = (const float*)d_in[4];
    const float* cmc_train = (const float*)d_in[5];
    const float* W_eeg     = (const float*)d_in[6];
    const float* a_eeg     = (const float*)d_in[7];
    const float* W_emg     = (const float*)d_in[8];
    const float* a_emg     = (const float*)d_in[9];
    const float* W_cmc     = (const float*)d_in[10];
    const float* b_cmc     = (const float*)d_in[11];
    const float* g0w1      = (const float*)d_in[12];
    const float* g0b1      = (const float*)d_in[13];
    const float* g0w2      = (const float*)d_in[14];
    const float* g0b2      = (const float*)d_in[15];
    const float* g1w1      = (const float*)d_in[16];
    const float* g1b1      = (const float*)d_in[17];
    const float* g1w2      = (const float*)d_in[18];
    const float* g1b2      = (const float*)d_in[19];
    const float* mlp0w     = (const float*)d_in[20];
    const float* mlp0b     = (const float*)d_in[21];
    const float* mlp1w     = (const float*)d_in[22];
    const float* mlp1b     = (const float*)d_in[23];
    const float* mlp2w     = (const float*)d_in[24];
    const float* mlp2b     = (const float*)d_in[25];
    const float* bng       = (const float*)d_in[26];
    const float* bnb       = (const float*)d_in[27];

    // k0: 600000 (Wt) + 3600 (cor) elements
    k0_prep<<<(12 * NC * NF + NG * NNODE * NNODE + 255) / 256, 256>>>(
        W_eeg, W_emg, W_cmc, cmc_train);

    k1_gemm<<<2880, 128>>>(eeg, emg, cmc);

    dim3 g2(NB, NG);
    k2_gat<<<g2, 128>>>(wpli_eeg, wpli_emg, a_eeg, a_emg, b_cmc,
                        g0w1, g0b1, g0w2, g0b2);

    k3_head<<<NB, 256>>>(g1w1, g1b1, g1w2, g1b2,
                         mlp0w, mlp0b, mlp1w, mlp1b, mlp2w, mlp2b,
                         bng, bnb, (float*)d_out);
}